// round 4
// baseline (speedup 1.0000x reference)
#include <cuda_runtime.h>

// Problem constants
#define Bdim 4
#define Cdim 16
#define Ldim 512
#define Hdim 1024

// Scratch: [2][B][L][C] floats, channel contiguous. 256 KB (lives in L2).
__device__ float g_scratch[2 * Bdim * Ldim * Cdim];

// Producer counters: one per (tensor, b, 16-row l-chunk). Target = 16 (one per c).
// Zero at module load; self-reset by last consumer each launch.
__device__ int g_prod[2][Bdim][32];
__device__ int g_cons[Bdim];

// ---------------------------------------------------------------------------
// Fused kernel. Block roles by bid (producers strictly precede their
// consumers in dispatch order; gap >= 1024 bids > one machine wave):
//   [   0,1024) dot b=0   [1024,2048) dot b=1   [2048,2560) add b=0
//   [2560,3584) dot b=2   [3584,4096) add b=1   [4096,5120) dot b=3
//   [5120,5632) add b=2   [5632,6144) add b=3
//
// Dot block: 8 warps x 2 rows = 16 consecutive l-rows of one (tensor,b,c).
// Add block: covers (b, 8 i's, 64 j's, 16 c) = 32 KB output (round-2 config).
// ---------------------------------------------------------------------------
__global__ void __launch_bounds__(256) fused_kernel(
    const float* __restrict__ start,
    const float* __restrict__ end,
    const float* __restrict__ v,
    float4* __restrict__ out)
{
    __shared__ float4 e_sm[64 * 4];   // [j][q]
    __shared__ float4 s_sm[8 * 4];    // [i][q]

    const unsigned bx  = blockIdx.x;
    const unsigned tid = threadIdx.x;

    unsigned b, local;
    int is_dot;
    if      (bx < 1024) { is_dot = 1; b = 0; local = bx;        }
    else if (bx < 2048) { is_dot = 1; b = 1; local = bx - 1024; }
    else if (bx < 2560) { is_dot = 0; b = 0; local = bx - 2048; }
    else if (bx < 3584) { is_dot = 1; b = 2; local = bx - 2560; }
    else if (bx < 4096) { is_dot = 0; b = 1; local = bx - 3584; }
    else if (bx < 5120) { is_dot = 1; b = 3; local = bx - 4096; }
    else if (bx < 5632) { is_dot = 0; b = 2; local = bx - 5120; }
    else                { is_dot = 0; b = 3; local = bx - 5632; }

    if (is_dot) {
        // ---- producer: 16 rows of dot products ----
        const unsigned t      = local >> 9;        // tensor 0/1
        const unsigned ul     = local & 511;
        const unsigned c      = ul >> 5;           // channel 0..15
        const unsigned lchunk = ul & 31;           // 16-row chunk 0..31
        const unsigned wid    = tid >> 5;
        const unsigned lane   = tid & 31;
        const unsigned l      = lchunk * 16 + wid * 2;

        const float* base = t ? end : start;
        const float4* row0 =
            (const float4*)(base + (size_t)((b * Cdim + c) * Ldim + l) * Hdim);
        const float4* v4 = (const float4*)(v + t * Hdim);
        const unsigned RS = Hdim / 4;

        float s0 = 0.f, s1 = 0.f;
#pragma unroll
        for (int k = 0; k < 8; k++) {
            const unsigned o = lane + 32 * k;
            float4 a0 = __ldcs(&row0[o]);
            float4 a1 = __ldcs(&row0[o + RS]);
            float4 w  = v4[o];
            s0 += a0.x * w.x + a0.y * w.y + a0.z * w.z + a0.w * w.w;
            s1 += a1.x * w.x + a1.y * w.y + a1.z * w.z + a1.w * w.w;
        }
#pragma unroll
        for (int o = 16; o; o >>= 1) {
            s0 += __shfl_xor_sync(0xFFFFFFFFu, s0, o);
            s1 += __shfl_xor_sync(0xFFFFFFFFu, s1, o);
        }
        if (lane == 0) {
            float* dst = &g_scratch[((t * Bdim + b) * Ldim + l) * Cdim + c];
            dst[0]    = s0;
            dst[Cdim] = s1;
        }
        __syncthreads();
        if (tid == 0) {
            __threadfence();
            atomicAdd(&g_prod[t][b][lchunk], 1);
        }
    } else {
        // ---- consumer: broadcast-add tile ----
        const unsigned jt = local & 7;    // 64-j tile
        const unsigned it = local >> 3;   // 8-i tile, 0..63

        if (tid == 0) {
            volatile int* ps = &g_prod[0][b][it >> 1];
            volatile int* pe = (volatile int*)&g_prod[1][b][jt * 4];
            while (*ps < 16 || pe[0] < 16 || pe[1] < 16 ||
                   pe[2] < 16 || pe[3] < 16)
                __nanosleep(128);
            __threadfence();
            // consumption accounting + self-reset for graph replay
            const int cnt = atomicAdd(&g_cons[b], 1);
            if (cnt == 511) {
                for (int k = 0; k < 32; k++) {
                    g_prod[0][b][k] = 0;
                    g_prod[1][b][k] = 0;
                }
                g_cons[b] = 0;
            }
        }
        __syncthreads();

        const float4* sc4 = (const float4*)g_scratch;  // [2][B][L][4] float4
        e_sm[tid] = sc4[((Bdim + b) * Ldim + jt * 64) * (Cdim / 4) + tid];
        if (tid < 32)
            s_sm[tid] = sc4[(b * Ldim + it * 8) * (Cdim / 4) + tid];
        __syncthreads();

        const unsigned q = tid & 3;
        const unsigned j = tid >> 2;
        const float4 e = e_sm[j * 4 + q];

        float4* dst = &out[(((b * Ldim + it * 8) * Ldim) + jt * 64 + j) * 4 + q];
#pragma unroll
        for (int i = 0; i < 8; i++) {
            float4 s = s_sm[i * 4 + q];
            dst[(size_t)i * Ldim * 4] =
                make_float4(s.x + e.x, s.y + e.y, s.z + e.z, s.w + e.w);
        }
    }
}

extern "C" void kernel_launch(void* const* d_in, const int* in_sizes, int n_in,
                              void* d_out, int out_size)
{
    const float* start = (const float*)d_in[0];
    const float* end   = (const float*)d_in[1];
    const float* v     = (const float*)d_in[2];
    float4* out = (float4*)d_out;

    // 4096 dot blocks + 2048 add blocks, dependency-ordered bids.
    fused_kernel<<<6144, 256>>>(start, end, v, out);
}

// round 5
// speedup vs baseline: 1.0885x; 1.0885x over previous
#include <cuda_runtime.h>
#include <cstdint>

// Problem constants
#define Bdim 4
#define Cdim 16
#define Ldim 512
#define Hdim 1024

// Scratch: [2][B][L][C] floats, channel contiguous. 256 KB (lives in L2).
__device__ float g_scratch[2 * Bdim * Ldim * Cdim];

// ---------------------------------------------------------------------------
// Kernel A (round-2 config, best measured): per-row dots, 2 rows per warp.
// warp w in [0, 32768): tensor = w>>14, rows idx0 = (w & 16383)*2, idx0+1.
// __ldcs streaming keeps the 268 MB out of L2's way.
// ---------------------------------------------------------------------------
__global__ void __launch_bounds__(256) dot_kernel(
    const float* __restrict__ start,
    const float* __restrict__ end,
    const float* __restrict__ v)
{
    const unsigned warp = (blockIdx.x * blockDim.x + threadIdx.x) >> 5;
    const unsigned lane = threadIdx.x & 31;

    const unsigned tensor = warp >> 14;              // 0 or 1
    const unsigned idx0   = (warp & 16383) * 2;      // first row within tensor

    const float* base = tensor ? end : start;
    const float4* row0 = (const float4*)(base + (size_t)idx0 * Hdim);
    const float4* row1 = (const float4*)(base + (size_t)(idx0 + 1) * Hdim);
    const float4* v4   = (const float4*)(v + tensor * Hdim);

    float sum0 = 0.f, sum1 = 0.f;
#pragma unroll
    for (int k = 0; k < Hdim / 4 / 32; k++) {        // 8 iterations
        float4 a0 = __ldcs(&row0[lane + 32 * k]);
        float4 a1 = __ldcs(&row1[lane + 32 * k]);
        float4 w  = v4[lane + 32 * k];
        sum0 += a0.x * w.x + a0.y * w.y + a0.z * w.z + a0.w * w.w;
        sum1 += a1.x * w.x + a1.y * w.y + a1.z * w.z + a1.w * w.w;
    }
#pragma unroll
    for (int o = 16; o; o >>= 1) {
        sum0 += __shfl_xor_sync(0xFFFFFFFFu, sum0, o);
        sum1 += __shfl_xor_sync(0xFFFFFFFFu, sum1, o);
    }

    if (lane == 0) {
        const unsigned b = idx0 >> 13;
        const unsigned c = (idx0 >> 9) & (Cdim - 1);
        const unsigned l = idx0 & (Ldim - 1);
        float* dst = &g_scratch[((tensor * Bdim + b) * Ldim + l) * Cdim + c];
        dst[0]    = sum0;
        dst[Cdim] = sum1;
    }
}

// ---------------------------------------------------------------------------
// Kernel B v4: bulk-store add. One block per (b,i). The 32 KB slice
// out[b,i,:,:] is contiguous -> build it in smem (STS, no L1 wavefront
// limit), then one cp.async.bulk shared->global pushes it to L2, bypassing
// the per-SM STG.128 L1 wavefront bottleneck entirely.
// Thread t has fixed channel quarter q = t&3; s float4 is loop-invariant.
// ---------------------------------------------------------------------------
__global__ void __launch_bounds__(256) add_kernel(float4* __restrict__ out)
{
    __shared__ alignas(128) float4 tile[2048];       // 32 KB

    const unsigned bx = blockIdx.x;                  // b*512 + i
    const unsigned b  = bx >> 9;
    const unsigned t  = threadIdx.x;

    const float4* sc4 = (const float4*)g_scratch;    // [2][B][L][4] float4
    const float4  s   = sc4[bx * 4 + (t & 3)];       // s[b,i, q]
    const float4* e   = &sc4[(Bdim + b) * Ldim * 4]; // e[b, j, q] linear

#pragma unroll
    for (int jj = 0; jj < 8; jj++) {                 // 2048 float4 / 256 thr
        const unsigned idx = jj * 256 + t;           // j*4 + q, q == t&3
        float4 ev = e[idx];
        tile[idx] = make_float4(s.x + ev.x, s.y + ev.y,
                                s.z + ev.z, s.w + ev.w);
    }
    __syncthreads();

    if (t == 0) {
        asm volatile("fence.proxy.async.shared::cta;" ::: "memory");
        uint32_t smem_addr;
        asm("{ .reg .u64 tmp; cvta.to.shared.u64 tmp, %1; cvt.u32.u64 %0, tmp; }"
            : "=r"(smem_addr) : "l"(tile));
        const char* dst = (const char*)out + (size_t)bx * 32768;
        asm volatile(
            "cp.async.bulk.global.shared::cta.bulk_group [%0], [%1], %2;"
            :: "l"(dst), "r"(smem_addr), "n"(32768) : "memory");
        asm volatile("cp.async.bulk.commit_group;" ::: "memory");
        asm volatile("cp.async.bulk.wait_group 0;" ::: "memory");
    }
}

extern "C" void kernel_launch(void* const* d_in, const int* in_sizes, int n_in,
                              void* d_out, int out_size)
{
    const float* start = (const float*)d_in[0];
    const float* end   = (const float*)d_in[1];
    const float* v     = (const float*)d_in[2];
    float4* out = (float4*)d_out;

    // Kernel A: 32768 warps (2 rows each) = 4096 blocks x 256 threads
    dot_kernel<<<4096, 256>>>(start, end, v);

    // Kernel B: one block per (b,i) = 2048 blocks x 256 threads
    add_kernel<<<2048, 256>>>(out);
}

// round 6
// speedup vs baseline: 1.0916x; 1.0028x over previous
#include <cuda_runtime.h>
#include <cstdint>

// Problem constants
#define Bdim 4
#define Cdim 16
#define Ldim 512
#define Hdim 1024

// Scratch: [2][B][L][C] floats, channel contiguous. 256 KB (lives in L2).
__device__ float g_scratch[2 * Bdim * Ldim * Cdim];

// ---------------------------------------------------------------------------
// Kernel A (round-2 config, best measured): per-row dots, 2 rows per warp.
// warp w in [0, 32768): tensor = w>>14, rows idx0 = (w & 16383)*2, idx0+1.
// __ldcs streaming keeps the 268 MB out of L2's way.
// ---------------------------------------------------------------------------
__global__ void __launch_bounds__(256) dot_kernel(
    const float* __restrict__ start,
    const float* __restrict__ end,
    const float* __restrict__ v)
{
    const unsigned warp = (blockIdx.x * blockDim.x + threadIdx.x) >> 5;
    const unsigned lane = threadIdx.x & 31;

    const unsigned tensor = warp >> 14;              // 0 or 1
    const unsigned idx0   = (warp & 16383) * 2;      // first row within tensor

    const float* base = tensor ? end : start;
    const float4* row0 = (const float4*)(base + (size_t)idx0 * Hdim);
    const float4* row1 = (const float4*)(base + (size_t)(idx0 + 1) * Hdim);
    const float4* v4   = (const float4*)(v + tensor * Hdim);

    float sum0 = 0.f, sum1 = 0.f;
#pragma unroll
    for (int k = 0; k < Hdim / 4 / 32; k++) {        // 8 iterations
        float4 a0 = __ldcs(&row0[lane + 32 * k]);
        float4 a1 = __ldcs(&row1[lane + 32 * k]);
        float4 w  = v4[lane + 32 * k];
        sum0 += a0.x * w.x + a0.y * w.y + a0.z * w.z + a0.w * w.w;
        sum1 += a1.x * w.x + a1.y * w.y + a1.z * w.z + a1.w * w.w;
    }
#pragma unroll
    for (int o = 16; o; o >>= 1) {
        sum0 += __shfl_xor_sync(0xFFFFFFFFu, sum0, o);
        sum1 += __shfl_xor_sync(0xFFFFFFFFu, sum1, o);
    }

    if (lane == 0) {
        const unsigned b = idx0 >> 13;
        const unsigned c = (idx0 >> 9) & (Cdim - 1);
        const unsigned l = idx0 & (Ldim - 1);
        float* dst = &g_scratch[((tensor * Bdim + b) * Ldim + l) * Cdim + c];
        dst[0]    = sum0;
        dst[Cdim] = sum1;
    }
}

// ---------------------------------------------------------------------------
// Kernel B v5: i-tiled bulk-store add, e held in registers.
// One block per (b, 8-i tile) = 256 blocks. Thread t (q = t&3) loads its 8
// e-float4s ONCE into registers, then for each of 8 i's computes the 32 KB
// contiguous slice out[b,i,:,:] into a double-buffered smem tile and drains
// it with one cp.async.bulk shared->global (no STG L1 wavefronts, e read
// from L2 exactly once per block).
// ---------------------------------------------------------------------------
__global__ void __launch_bounds__(256) add_kernel(float4* __restrict__ out)
{
    __shared__ alignas(128) float4 tile[2][2048];    // 2 x 32 KB

    const unsigned bx = blockIdx.x;                  // b*64 + itile
    const unsigned b  = bx >> 6;
    const unsigned t  = threadIdx.x;

    const float4* sc4 = (const float4*)g_scratch;    // [2][B][L][4] float4
    const float4* e   = &sc4[(Bdim + b) * Ldim * 4]; // e[b, j*4+q] linear
    const float4* sv  = &sc4[(size_t)bx * 8 * 4 + (t & 3)];  // s[b, i0+i, q]

    // e tile -> registers (8 float4 = 32 regs per thread)
    float4 er[8];
#pragma unroll
    for (int jj = 0; jj < 8; jj++)
        er[jj] = e[jj * 256 + t];

    uint32_t smem_base;
    asm("{ .reg .u64 tmp; cvta.to.shared.u64 tmp, %1; cvt.u32.u64 %0, tmp; }"
        : "=r"(smem_base) : "l"(&tile[0][0]));

#pragma unroll
    for (int i = 0; i < 8; i++) {
        const unsigned p = i & 1;

        if (i >= 2) {                       // buffer p must have drained
            if (t == 0)
                asm volatile("cp.async.bulk.wait_group 1;" ::: "memory");
            __syncthreads();
        }

        const float4 s = sv[i * 4];         // broadcast, L1/L2 hit
        float4* buf = tile[p];
#pragma unroll
        for (int jj = 0; jj < 8; jj++) {
            float4 ev = er[jj];
            buf[jj * 256 + t] = make_float4(s.x + ev.x, s.y + ev.y,
                                            s.z + ev.z, s.w + ev.w);
        }
        __syncthreads();

        if (t == 0) {
            asm volatile("fence.proxy.async.shared::cta;" ::: "memory");
            const char* dst = (const char*)out + ((size_t)bx * 8 + i) * 32768;
            asm volatile(
                "cp.async.bulk.global.shared::cta.bulk_group [%0], [%1], %2;"
                :: "l"(dst), "r"(smem_base + p * 32768), "n"(32768) : "memory");
            asm volatile("cp.async.bulk.commit_group;" ::: "memory");
        }
    }
    if (t == 0)
        asm volatile("cp.async.bulk.wait_group 0;" ::: "memory");
}

extern "C" void kernel_launch(void* const* d_in, const int* in_sizes, int n_in,
                              void* d_out, int out_size)
{
    const float* start = (const float*)d_in[0];
    const float* end   = (const float*)d_in[1];
    const float* v     = (const float*)d_in[2];
    float4* out = (float4*)d_out;

    // Kernel A: 32768 warps (2 rows each) = 4096 blocks x 256 threads
    dot_kernel<<<4096, 256>>>(start, end, v);

    // Kernel B: one block per (b, 8-i tile) = 256 blocks x 256 threads
    add_kernel<<<256, 256>>>(out);
}

// round 7
// speedup vs baseline: 1.1147x; 1.0212x over previous
#include <cuda_runtime.h>

// Problem constants
#define Bdim 4
#define Cdim 16
#define Ldim 512
#define Hdim 1024

// Scratch: [2][B][L][C] floats, channel contiguous. 256 KB (lives in L2).
__device__ float g_scratch[2 * Bdim * Ldim * Cdim];

// ---------------------------------------------------------------------------
// Kernel A v6: per-row dots, 2 rows per warp; v preloaded to registers;
// all 16 row-loads front-batched before any FMA (MLP_eff ~16/warp).
// warp w in [0, 32768): tensor = w>>14, rows idx0 = (w & 16383)*2, idx0+1.
// ---------------------------------------------------------------------------
__global__ void __launch_bounds__(256) dot_kernel(
    const float* __restrict__ start,
    const float* __restrict__ end,
    const float* __restrict__ v)
{
    const unsigned warp = (blockIdx.x * blockDim.x + threadIdx.x) >> 5;
    const unsigned lane = threadIdx.x & 31;

    const unsigned tensor = warp >> 14;              // 0 or 1
    const unsigned idx0   = (warp & 16383) * 2;      // first row within tensor

    const float* base = tensor ? end : start;
    const float4* row0 = (const float4*)(base + (size_t)idx0 * Hdim);
    const float4* row1 = (const float4*)(base + (size_t)(idx0 + 1) * Hdim);
    const float4* v4   = (const float4*)(v + tensor * Hdim);

    // v is loop-invariant: 8 float4 = 32 regs, loaded once (L1/L2 hits).
    float4 w[8];
#pragma unroll
    for (int k = 0; k < 8; k++)
        w[k] = v4[lane + 32 * k];

    // Front-batch all 16 streaming row loads (no dependent math between).
    float4 a0[8], a1[8];
#pragma unroll
    for (int k = 0; k < 8; k++) {
        a0[k] = __ldcs(&row0[lane + 32 * k]);
        a1[k] = __ldcs(&row1[lane + 32 * k]);
    }

    float sum0 = 0.f, sum1 = 0.f;
#pragma unroll
    for (int k = 0; k < 8; k++) {
        sum0 += a0[k].x * w[k].x + a0[k].y * w[k].y
              + a0[k].z * w[k].z + a0[k].w * w[k].w;
        sum1 += a1[k].x * w[k].x + a1[k].y * w[k].y
              + a1[k].z * w[k].z + a1[k].w * w[k].w;
    }
#pragma unroll
    for (int o = 16; o; o >>= 1) {
        sum0 += __shfl_xor_sync(0xFFFFFFFFu, sum0, o);
        sum1 += __shfl_xor_sync(0xFFFFFFFFu, sum1, o);
    }

    if (lane == 0) {
        const unsigned b = idx0 >> 13;
        const unsigned c = (idx0 >> 9) & (Cdim - 1);
        const unsigned l = idx0 & (Ldim - 1);
        float* dst = &g_scratch[((tensor * Bdim + b) * Ldim + l) * Cdim + c];
        dst[0]    = sum0;
        dst[Cdim] = sum1;
    }
}

// ---------------------------------------------------------------------------
// Kernel B (round-2 version, best measured): smem-tiled broadcast add.
// Block covers (b, 8 i's, 64 j's, all 16 c) = 32 KB output.
// ---------------------------------------------------------------------------
__global__ void __launch_bounds__(256) add_kernel(float4* __restrict__ out)
{
    __shared__ float4 e_sm[64 * 4];   // [j][q]
    __shared__ float4 s_sm[8 * 4];    // [i][q]

    const unsigned bx = blockIdx.x;
    const unsigned jt = bx & 7;           // j tile (64 j each)
    const unsigned it = (bx >> 3) & 63;   // i tile (8 i each)
    const unsigned b  = bx >> 9;

    const unsigned t = threadIdx.x;
    const float4* sc4 = (const float4*)g_scratch;   // [2][B][L][4] float4

    e_sm[t] = sc4[((Bdim + b) * Ldim + jt * 64) * (Cdim / 4) + t];
    if (t < 32)
        s_sm[t] = sc4[(b * Ldim + it * 8) * (Cdim / 4) + t];
    __syncthreads();

    const unsigned q = t & 3;
    const unsigned j = t >> 2;
    const float4 e = e_sm[j * 4 + q];

    float4* dst = &out[(((b * Ldim + it * 8) * Ldim) + jt * 64 + j) * 4 + q];

#pragma unroll
    for (int i = 0; i < 8; i++) {
        float4 s = s_sm[i * 4 + q];
        dst[(size_t)i * Ldim * 4] =
            make_float4(s.x + e.x, s.y + e.y, s.z + e.z, s.w + e.w);
    }
}

extern "C" void kernel_launch(void* const* d_in, const int* in_sizes, int n_in,
                              void* d_out, int out_size)
{
    const float* start = (const float*)d_in[0];
    const float* end   = (const float*)d_in[1];
    const float* v     = (const float*)d_in[2];
    float4* out = (float4*)d_out;

    // Kernel A: 32768 warps (2 rows each) = 4096 blocks x 256 threads
    dot_kernel<<<4096, 256>>>(start, end, v);

    // Kernel B: 4 b x 64 i-tiles x 8 j-tiles = 2048 blocks x 256 threads
    add_kernel<<<2048, 256>>>(out);
}